// round 3
// baseline (speedup 1.0000x reference)
#include <cuda_runtime.h>
#include <cuda_bf16.h>

// Problem constants (fixed by reference setup_inputs)
#define HH   1024
#define WW   1024
#define NC   8
#define NCOL (WW * NC)      // 8192 flat columns in [y][x][c] layout
#define NSEG 16
#define SEGH (HH / NSEG)    // 64
#define NPOOL 7

// Scratch: SAT in channel-last layout [y][x][c], fp32. 32 MB (fits L2).
__device__ float g_sat[(size_t)HH * NCOL];
// Per-(column, segment) sums -> exclusive offsets
__device__ float g_seg[NSEG * NCOL];

// ---------------------------------------------------------------------------
// Pass 1: inclusive row scan (along x) for each y, all 8 channels, then
// transpose-write to channel-last layout. One block per y, 1024 threads.
// ---------------------------------------------------------------------------
__global__ void __launch_bounds__(1024) rowscan_kernel(const float* __restrict__ in) {
    __shared__ float rowbuf[NC][WW];   // 32 KB
    __shared__ float wsum[33];

    const int y    = blockIdx.x;
    const int t    = threadIdx.x;
    const int lane = t & 31;
    const int wid  = t >> 5;

    #pragma unroll 1
    for (int c = 0; c < NC; ++c) {
        float v = in[(size_t)c * (HH * WW) + (size_t)y * WW + t];
        // warp inclusive scan
        #pragma unroll
        for (int d = 1; d < 32; d <<= 1) {
            float nb = __shfl_up_sync(0xffffffffu, v, d);
            if (lane >= d) v += nb;
        }
        if (lane == 31) wsum[wid] = v;
        __syncthreads();
        if (wid == 0) {
            float w = wsum[lane];
            #pragma unroll
            for (int d = 1; d < 32; d <<= 1) {
                float nb = __shfl_up_sync(0xffffffffu, w, d);
                if (lane >= d) w += nb;
            }
            wsum[lane] = w;
        }
        __syncthreads();
        if (wid > 0) v += wsum[wid - 1];
        rowbuf[c][t] = v;
        __syncthreads();   // protect wsum before next channel's writes
    }

    // Transpose write: thread t owns column x=t (it wrote rowbuf[c][t] itself).
    float4 a, b;
    a.x = rowbuf[0][t]; a.y = rowbuf[1][t]; a.z = rowbuf[2][t]; a.w = rowbuf[3][t];
    b.x = rowbuf[4][t]; b.y = rowbuf[5][t]; b.z = rowbuf[6][t]; b.w = rowbuf[7][t];
    float4* out4 = (float4*)(g_sat + (size_t)y * NCOL);
    out4[t * 2]     = a;
    out4[t * 2 + 1] = b;
}

// ---------------------------------------------------------------------------
// Pass 2a: per-(flat column f, segment) sums of 64 rows. Kahan fp32.
// ---------------------------------------------------------------------------
__global__ void __launch_bounds__(256) colpartial_kernel() {
    const int g   = blockIdx.x * blockDim.x + threadIdx.x;
    const int f   = g & (NCOL - 1);
    const int seg = g >> 13;                    // NCOL = 2^13
    const float* p = g_sat + (size_t)seg * SEGH * NCOL + f;
    float s = 0.f, comp = 0.f;
    #pragma unroll 8
    for (int k = 0; k < SEGH; ++k) {
        float v  = p[(size_t)k * NCOL];
        float yv = v - comp;
        float tt = s + yv;
        comp = (tt - s) - yv;
        s = tt;
    }
    g_seg[(size_t)seg * NCOL + f] = s;
}

// ---------------------------------------------------------------------------
// Pass 2b: exclusive scan over the 16 segment sums of each column (double —
// only 131K DADDs total, negligible even at B300's cut FP64 rate).
// ---------------------------------------------------------------------------
__global__ void __launch_bounds__(256) segscan_kernel() {
    const int f = blockIdx.x * blockDim.x + threadIdx.x;
    double run = 0.0;
    #pragma unroll
    for (int sgi = 0; sgi < NSEG; ++sgi) {
        float tv = g_seg[(size_t)sgi * NCOL + f];
        g_seg[(size_t)sgi * NCOL + f] = (float)run;
        run += (double)tv;
    }
}

// ---------------------------------------------------------------------------
// Pass 2c: finalize column cumsum in place (Kahan, seeded by segment offset).
// ---------------------------------------------------------------------------
__global__ void __launch_bounds__(256) colfinal_kernel() {
    const int g   = blockIdx.x * blockDim.x + threadIdx.x;
    const int f   = g & (NCOL - 1);
    const int seg = g >> 13;
    float* p = g_sat + (size_t)seg * SEGH * NCOL + f;
    float s = g_seg[(size_t)seg * NCOL + f];
    float comp = 0.f;
    #pragma unroll 8
    for (int k = 0; k < SEGH; ++k) {
        float v  = p[(size_t)k * NCOL];
        float yv = v - comp;
        float tt = s + yv;
        comp = (tt - s) - yv;
        s = tt;
        p[(size_t)k * NCOL] = s;
    }
}

// ---------------------------------------------------------------------------
// Pass 3: adaptive 7x7 ROI pooling + final mean. One warp per ROI.
// SAT lookup semantics: padded sat(y, x) = sum over rows [0,y), cols [0,x);
// stored g_sat holds inclusive SAT, so sat(y,x) = g_sat[y-1][x-1] (0 if y==0||x==0).
// ---------------------------------------------------------------------------
__device__ __forceinline__ void load8(int y, int x, float v[8]) {
    if (y > 0 && x > 0) {
        const float4* p = (const float4*)(g_sat + ((size_t)(y - 1) * WW + (x - 1)) * NC);
        float4 a = p[0], b = p[1];
        v[0] = a.x; v[1] = a.y; v[2] = a.z; v[3] = a.w;
        v[4] = b.x; v[5] = b.y; v[6] = b.z; v[7] = b.w;
    } else {
        #pragma unroll
        for (int c = 0; c < 8; ++c) v[c] = 0.f;
    }
}

__global__ void __launch_bounds__(256) pool_kernel(const int* __restrict__ rois,
                                                   float* __restrict__ out, int n) {
    const int warp = (blockIdx.x * blockDim.x + threadIdx.x) >> 5;
    const int lane = threadIdx.x & 31;
    if (warp >= n) return;

    // rois is int32 [n,4] (JAX default x64-disabled: astype(int64) -> int32)
    const int4 R = ((const int4*)rois)[warp];
    const int ymin = R.x >> 5;            // // FEAT_STRIDE (=32)
    const int xmin = R.y >> 5;
    const int ymax = (R.z >> 5) + 1;      // exclusive
    const int xmax = (R.w >> 5) + 1;
    const int leny = ymax - ymin;
    const int lenx = xmax - xmin;

    float acc[8];
    #pragma unroll
    for (int c = 0; c < 8; ++c) acc[c] = 0.f;

    for (int bin = lane; bin < 49; bin += 32) {
        const int i = bin / 7;
        const int j = bin - i * 7;
        const int ylo = ymin + (i * leny) / NPOOL;
        const int yhi = ymin + ((i + 1) * leny + NPOOL - 1) / NPOOL;
        const int xlo = xmin + (j * lenx) / NPOOL;
        const int xhi = xmin + ((j + 1) * lenx + NPOOL - 1) / NPOOL;

        float Shh[8], Slh[8], Shl[8], Sll[8];
        load8(yhi, xhi, Shh);
        load8(ylo, xhi, Slh);
        load8(yhi, xlo, Shl);
        load8(ylo, xlo, Sll);

        const int   area = (yhi - ylo) * (xhi - xlo);
        const float w    = 1.f / (float)area;
        #pragma unroll
        for (int c = 0; c < 8; ++c)
            acc[c] += w * ((Shh[c] - Slh[c]) - (Shl[c] - Sll[c]));
    }

    #pragma unroll
    for (int c = 0; c < 8; ++c) {
        #pragma unroll
        for (int d = 16; d; d >>= 1)
            acc[c] += __shfl_xor_sync(0xffffffffu, acc[c], d);
    }

    if (lane == 0) {
        const float inv49 = 1.f / 49.f;
        float4 o0 = make_float4(acc[0] * inv49, acc[1] * inv49, acc[2] * inv49, acc[3] * inv49);
        float4 o1 = make_float4(acc[4] * inv49, acc[5] * inv49, acc[6] * inv49, acc[7] * inv49);
        float4* o = (float4*)(out + (size_t)warp * 8);
        o[0] = o0;
        o[1] = o1;
    }
}

// ---------------------------------------------------------------------------
extern "C" void kernel_launch(void* const* d_in, const int* in_sizes, int n_in,
                              void* d_out, int out_size) {
    const float* conv = (const float*)d_in[0];   // [8,1024,1024] fp32
    const int*   rois = (const int*)d_in[1];     // [n,4] int32
    float*       out  = (float*)d_out;           // [n,8] fp32
    const int n = in_sizes[1] / 4;

    rowscan_kernel   <<<HH, 1024>>>(conv);
    colpartial_kernel<<<(NSEG * NCOL) / 256, 256>>>();
    segscan_kernel   <<<NCOL / 256, 256>>>();
    colfinal_kernel  <<<(NSEG * NCOL) / 256, 256>>>();
    pool_kernel      <<<(n + 7) / 8, 256>>>(rois, out, n);
}

// round 4
// speedup vs baseline: 1.3139x; 1.3139x over previous
#include <cuda_runtime.h>
#include <cuda_bf16.h>

// Problem constants (fixed by reference setup_inputs)
#define HH   1024
#define WW   1024
#define NC   8
#define NCOL (WW * NC)      // 8192 flat columns in [y][x][c] layout
#define NSEG 16
#define SEGH (HH / NSEG)    // 64
#define NPOOL 7

// Scratch: SAT in channel-last layout [y][x][c], fp32. 32 MB (fits L2).
__device__ float g_sat[(size_t)HH * NCOL];
// Decoupled-lookback links: per (seg, flat column) packed {float_bits:32 | ready:1}.
__device__ unsigned long long g_link[NSEG * NCOL];   // 1 MB

// ---------------------------------------------------------------------------
// Pass 1: inclusive row scan (along x) for each y, all 8 channels, register
// resident, transpose-write to channel-last layout. One block per y.
// Also resets the lookback links for the colscan pass (stream order makes
// the reset visible before colscan launches).
// ---------------------------------------------------------------------------
__global__ void __launch_bounds__(1024) rowscan_kernel(const float* __restrict__ in) {
    __shared__ float wsum[NC][33];

    const int y    = blockIdx.x;
    const int t    = threadIdx.x;
    const int lane = t & 31;
    const int wid  = t >> 5;

    // Reset lookback links: NSEG*NCOL = 131072 entries / 1024 blocks = 128 each.
    if (t < (NSEG * NCOL) / HH)
        g_link[(size_t)y * ((NSEG * NCOL) / HH) + t] = 0ull;

    float v[NC];
    #pragma unroll
    for (int c = 0; c < NC; ++c)
        v[c] = in[(size_t)c * (HH * WW) + (size_t)y * WW + t];

    // Warp inclusive scans, all channels (batched -> 1 barrier pair total)
    #pragma unroll
    for (int c = 0; c < NC; ++c) {
        #pragma unroll
        for (int d = 1; d < 32; d <<= 1) {
            float nb = __shfl_up_sync(0xffffffffu, v[c], d);
            if (lane >= d) v[c] += nb;
        }
        if (lane == 31) wsum[c][wid] = v[c];
    }
    __syncthreads();
    if (wid == 0) {
        #pragma unroll
        for (int c = 0; c < NC; ++c) {
            float w = wsum[c][lane];
            #pragma unroll
            for (int d = 1; d < 32; d <<= 1) {
                float nb = __shfl_up_sync(0xffffffffu, w, d);
                if (lane >= d) w += nb;
            }
            wsum[c][lane] = w;
        }
    }
    __syncthreads();
    if (wid > 0) {
        #pragma unroll
        for (int c = 0; c < NC; ++c)
            v[c] += wsum[c][wid - 1];
    }

    // Transpose write straight from registers (thread t owns column x=t).
    float4 a = make_float4(v[0], v[1], v[2], v[3]);
    float4 b = make_float4(v[4], v[5], v[6], v[7]);
    float4* out4 = (float4*)(g_sat + (size_t)y * NCOL);
    out4[t * 2]     = a;
    out4[t * 2 + 1] = b;
}

// ---------------------------------------------------------------------------
// Pass 2 (fused): single-pass column cumsum with decoupled lookback.
// Block = 1 segment (64 rows) x 256 columns. seg ascends with blockIdx so
// every dependency points to a lower block id (deadlock-free).
// Reads SAT once, writes SAT once (vs 3 passes before).
// ---------------------------------------------------------------------------
__global__ void __launch_bounds__(256) colscan_kernel() {
    const int tid   = threadIdx.x;
    const int seg   = blockIdx.x >> 5;       // NCOL/256 = 32 chunks per seg
    const int chunk = blockIdx.x & 31;
    const int f     = chunk * 256 + tid;

    float* base = g_sat + (size_t)seg * SEGH * NCOL + f;

    // Local inclusive prefix over the 64 segment rows (Kahan, reg-resident).
    float pref[SEGH];
    float s = 0.f, comp = 0.f;
    #pragma unroll
    for (int k = 0; k < SEGH; ++k) {
        float v  = __ldcg(base + (size_t)k * NCOL);
        float yv = v - comp;
        float tt = s + yv;
        comp = (tt - s) - yv;
        s = tt;
        pref[k] = s;
    }

    // Lookback: wait for previous segment's inclusive prefix for this column.
    float off = 0.f;
    if (seg > 0) {
        unsigned long long u;
        do {
            u = atomicAdd(&g_link[(size_t)(seg - 1) * NCOL + f], 0ull);
        } while (!(u & 1ull));
        off = __uint_as_float((unsigned)(u >> 32));
    }

    // Publish our inclusive prefix (single-word atomic: value+flag together).
    if (seg < NSEG - 1) {
        unsigned long long pub =
            ((unsigned long long)__float_as_uint(off + s) << 32) | 1ull;
        atomicExch(&g_link[(size_t)seg * NCOL + f], pub);
    }

    // Finalize in place.
    #pragma unroll
    for (int k = 0; k < SEGH; ++k)
        __stcg(base + (size_t)k * NCOL, pref[k] + off);
}

// ---------------------------------------------------------------------------
// Pass 3: adaptive 7x7 ROI pooling + final mean. One warp per ROI.
// stored g_sat holds inclusive SAT; padded sat(y,x) = g_sat[y-1][x-1]
// (0 if y==0 || x==0).
// ---------------------------------------------------------------------------
__device__ __forceinline__ void load8(int y, int x, float v[8]) {
    if (y > 0 && x > 0) {
        const float4* p = (const float4*)(g_sat + ((size_t)(y - 1) * WW + (x - 1)) * NC);
        float4 a = p[0], b = p[1];
        v[0] = a.x; v[1] = a.y; v[2] = a.z; v[3] = a.w;
        v[4] = b.x; v[5] = b.y; v[6] = b.z; v[7] = b.w;
    } else {
        #pragma unroll
        for (int c = 0; c < 8; ++c) v[c] = 0.f;
    }
}

__global__ void __launch_bounds__(256) pool_kernel(const int* __restrict__ rois,
                                                   float* __restrict__ out, int n) {
    const int warp = (blockIdx.x * blockDim.x + threadIdx.x) >> 5;
    const int lane = threadIdx.x & 31;
    if (warp >= n) return;

    // rois is int32 [n,4] (JAX default x64-disabled: astype(int64) -> int32)
    const int4 R = ((const int4*)rois)[warp];
    const int ymin = R.x >> 5;            // // FEAT_STRIDE (=32)
    const int xmin = R.y >> 5;
    const int ymax = (R.z >> 5) + 1;      // exclusive
    const int xmax = (R.w >> 5) + 1;
    const int leny = ymax - ymin;
    const int lenx = xmax - xmin;

    float acc[8];
    #pragma unroll
    for (int c = 0; c < 8; ++c) acc[c] = 0.f;

    for (int bin = lane; bin < 49; bin += 32) {
        const int i = bin / 7;
        const int j = bin - i * 7;
        const int ylo = ymin + (i * leny) / NPOOL;
        const int yhi = ymin + ((i + 1) * leny + NPOOL - 1) / NPOOL;
        const int xlo = xmin + (j * lenx) / NPOOL;
        const int xhi = xmin + ((j + 1) * lenx + NPOOL - 1) / NPOOL;

        float Shh[8], Slh[8], Shl[8], Sll[8];
        load8(yhi, xhi, Shh);
        load8(ylo, xhi, Slh);
        load8(yhi, xlo, Shl);
        load8(ylo, xlo, Sll);

        const int   area = (yhi - ylo) * (xhi - xlo);
        const float w    = 1.f / (float)area;
        #pragma unroll
        for (int c = 0; c < 8; ++c)
            acc[c] += w * ((Shh[c] - Slh[c]) - (Shl[c] - Sll[c]));
    }

    #pragma unroll
    for (int c = 0; c < 8; ++c) {
        #pragma unroll
        for (int d = 16; d; d >>= 1)
            acc[c] += __shfl_xor_sync(0xffffffffu, acc[c], d);
    }

    if (lane == 0) {
        const float inv49 = 1.f / 49.f;
        float4 o0 = make_float4(acc[0] * inv49, acc[1] * inv49, acc[2] * inv49, acc[3] * inv49);
        float4 o1 = make_float4(acc[4] * inv49, acc[5] * inv49, acc[6] * inv49, acc[7] * inv49);
        float4* o = (float4*)(out + (size_t)warp * 8);
        o[0] = o0;
        o[1] = o1;
    }
}

// ---------------------------------------------------------------------------
extern "C" void kernel_launch(void* const* d_in, const int* in_sizes, int n_in,
                              void* d_out, int out_size) {
    const float* conv = (const float*)d_in[0];   // [8,1024,1024] fp32
    const int*   rois = (const int*)d_in[1];     // [n,4] int32
    float*       out  = (float*)d_out;           // [n,8] fp32
    const int n = in_sizes[1] / 4;

    rowscan_kernel<<<HH, 1024>>>(conv);
    colscan_kernel<<<NSEG * (NCOL / 256), 256>>>();
    pool_kernel   <<<(n + 7) / 8, 256>>>(rois, out, n);
}

// round 5
// speedup vs baseline: 1.5199x; 1.1568x over previous
#include <cuda_runtime.h>
#include <cuda_bf16.h>

// Problem constants (fixed by reference setup_inputs)
#define HH   1024
#define WW   1024
#define NC   8
#define NCOL (WW * NC)      // 8192 flat columns in [y][x][c] layout
#define NSEG 16
#define SEGH (HH / NSEG)    // 64
#define NPOOL 7

// Scratch: SAT in channel-last layout [y][x][c], fp32. 32 MB (fits L2).
__device__ float g_sat[(size_t)HH * NCOL];
// Decoupled-lookback links: per (seg, flat column) packed {float_bits:32 | ready:1}.
__device__ unsigned long long g_link[NSEG * NCOL];   // 1 MB

// ---------------------------------------------------------------------------
// Pass 1: inclusive row scan (along x), 4 elements per thread (float4),
// register-sequential prefix + warp scan of totals + 8-warp block combine.
// Transpose to channel-last layout via padded smem for coalesced stores.
// One block (256 threads) per row y. Also resets lookback links.
// ---------------------------------------------------------------------------
__global__ void __launch_bounds__(256) rowscan_kernel(const float* __restrict__ in) {
    __shared__ float wsum[NC][8];
    __shared__ float sbuf[256 * 33];      // padded transpose buffer (33 KB)

    const int y    = blockIdx.x;
    const int t    = threadIdx.x;
    const int lane = t & 31;
    const int wid  = t >> 5;

    // Reset lookback links: 131072 entries / 1024 rows = 128 per row.
    if (t < 128)
        g_link[(size_t)y * 128 + t] = 0ull;

    // Load 4 consecutive x per channel; sequential in-register prefix.
    float4 v[NC];
    float  tot[NC], excl[NC];
    #pragma unroll
    for (int c = 0; c < NC; ++c) {
        v[c] = ((const float4*)(in + (size_t)c * (HH * WW) + (size_t)y * WW))[t];
        v[c].y += v[c].x;
        v[c].z += v[c].y;
        v[c].w += v[c].z;
        tot[c] = v[c].w;
    }

    // Warp inclusive scan of per-thread totals; derive exclusive offset.
    #pragma unroll
    for (int c = 0; c < NC; ++c) {
        float s = tot[c];
        #pragma unroll
        for (int d = 1; d < 32; d <<= 1) {
            float nb = __shfl_up_sync(0xffffffffu, s, d);
            if (lane >= d) s += nb;
        }
        excl[c] = s - tot[c];
        if (lane == 31) wsum[c][wid] = s;
    }
    __syncthreads();

    // Warp 0 scans the 8 warp totals per channel (width-8 groups).
    if (wid == 0) {
        #pragma unroll
        for (int c = 0; c < NC; ++c) {
            float w = (lane < 8) ? wsum[c][lane] : 0.f;
            #pragma unroll
            for (int d = 1; d < 8; d <<= 1) {
                float nb = __shfl_up_sync(0xffffffffu, w, d);
                if ((lane & 7) >= d) w += nb;
            }
            if (lane < 8) wsum[c][lane] = w;
        }
    }
    __syncthreads();

    // Final values -> padded smem in [x][c] order: idx = 33*t + 8*i + c.
    // (write banks = lane + const : conflict-free)
    #pragma unroll
    for (int c = 0; c < NC; ++c) {
        float off = excl[c] + (wid ? wsum[c][wid - 1] : 0.f);
        sbuf[33 * t + c]      = v[c].x + off;
        sbuf[33 * t + 8 + c]  = v[c].y + off;
        sbuf[33 * t + 16 + c] = v[c].z + off;
        sbuf[33 * t + 24 + c] = v[c].w + off;
    }
    __syncthreads();

    // Coalesced float4 stores: output float index o -> smem idx = o + o/32.
    float4* out4 = (float4*)(g_sat + (size_t)y * NCOL);
    #pragma unroll
    for (int j = 0; j < 8; ++j) {
        const int o   = (j * 256 + t) * 4;
        const int idx = o + (o >> 5);
        out4[j * 256 + t] = make_float4(sbuf[idx], sbuf[idx + 1],
                                        sbuf[idx + 2], sbuf[idx + 3]);
    }
}

// ---------------------------------------------------------------------------
// Pass 2 (fused): single-pass column cumsum with decoupled lookback.
// Block = 1 segment (64 rows) x 256 columns. seg ascends with blockIdx so
// every dependency points to a lower block id (deadlock-free).
// ---------------------------------------------------------------------------
__global__ void __launch_bounds__(256) colscan_kernel() {
    const int tid   = threadIdx.x;
    const int seg   = blockIdx.x >> 5;       // NCOL/256 = 32 chunks per seg
    const int chunk = blockIdx.x & 31;
    const int f     = chunk * 256 + tid;

    float* base = g_sat + (size_t)seg * SEGH * NCOL + f;

    // Local inclusive prefix over the 64 segment rows (Kahan, reg-resident).
    float pref[SEGH];
    float s = 0.f, comp = 0.f;
    #pragma unroll
    for (int k = 0; k < SEGH; ++k) {
        float v  = __ldcg(base + (size_t)k * NCOL);
        float yv = v - comp;
        float tt = s + yv;
        comp = (tt - s) - yv;
        s = tt;
        pref[k] = s;
    }

    // Lookback: wait for previous segment's inclusive prefix for this column.
    float off = 0.f;
    if (seg > 0) {
        unsigned long long u;
        do {
            u = atomicAdd(&g_link[(size_t)(seg - 1) * NCOL + f], 0ull);
        } while (!(u & 1ull));
        off = __uint_as_float((unsigned)(u >> 32));
    }

    // Publish our inclusive prefix (single-word atomic: value+flag together).
    if (seg < NSEG - 1) {
        unsigned long long pub =
            ((unsigned long long)__float_as_uint(off + s) << 32) | 1ull;
        atomicExch(&g_link[(size_t)seg * NCOL + f], pub);
    }

    // Finalize in place.
    #pragma unroll
    for (int k = 0; k < SEGH; ++k)
        __stcg(base + (size_t)k * NCOL, pref[k] + off);
}

// ---------------------------------------------------------------------------
// Pass 3: adaptive 7x7 ROI pooling + final mean. One warp per ROI.
// stored g_sat holds inclusive SAT; padded sat(y,x) = g_sat[y-1][x-1]
// (0 if y==0 || x==0).
// ---------------------------------------------------------------------------
__device__ __forceinline__ void load8(int y, int x, float v[8]) {
    if (y > 0 && x > 0) {
        const float4* p = (const float4*)(g_sat + ((size_t)(y - 1) * WW + (x - 1)) * NC);
        float4 a = p[0], b = p[1];
        v[0] = a.x; v[1] = a.y; v[2] = a.z; v[3] = a.w;
        v[4] = b.x; v[5] = b.y; v[6] = b.z; v[7] = b.w;
    } else {
        #pragma unroll
        for (int c = 0; c < 8; ++c) v[c] = 0.f;
    }
}

__global__ void __launch_bounds__(256) pool_kernel(const int* __restrict__ rois,
                                                   float* __restrict__ out, int n) {
    const int warp = (blockIdx.x * blockDim.x + threadIdx.x) >> 5;
    const int lane = threadIdx.x & 31;
    if (warp >= n) return;

    // rois is int32 [n,4]
    const int4 R = ((const int4*)rois)[warp];
    const int ymin = R.x >> 5;            // // FEAT_STRIDE (=32)
    const int xmin = R.y >> 5;
    const int ymax = (R.z >> 5) + 1;      // exclusive
    const int xmax = (R.w >> 5) + 1;
    const int leny = ymax - ymin;
    const int lenx = xmax - xmin;

    float acc[8];
    #pragma unroll
    for (int c = 0; c < 8; ++c) acc[c] = 0.f;

    for (int bin = lane; bin < 49; bin += 32) {
        const int i = bin / 7;
        const int j = bin - i * 7;
        const int ylo = ymin + (i * leny) / NPOOL;
        const int yhi = ymin + ((i + 1) * leny + NPOOL - 1) / NPOOL;
        const int xlo = xmin + (j * lenx) / NPOOL;
        const int xhi = xmin + ((j + 1) * lenx + NPOOL - 1) / NPOOL;

        float Shh[8], Slh[8], Shl[8], Sll[8];
        load8(yhi, xhi, Shh);
        load8(ylo, xhi, Slh);
        load8(yhi, xlo, Shl);
        load8(ylo, xlo, Sll);

        const int   area = (yhi - ylo) * (xhi - xlo);
        const float w    = 1.f / (float)area;
        #pragma unroll
        for (int c = 0; c < 8; ++c)
            acc[c] += w * ((Shh[c] - Slh[c]) - (Shl[c] - Sll[c]));
    }

    #pragma unroll
    for (int c = 0; c < 8; ++c) {
        #pragma unroll
        for (int d = 16; d; d >>= 1)
            acc[c] += __shfl_xor_sync(0xffffffffu, acc[c], d);
    }

    if (lane == 0) {
        const float inv49 = 1.f / 49.f;
        float4 o0 = make_float4(acc[0] * inv49, acc[1] * inv49, acc[2] * inv49, acc[3] * inv49);
        float4 o1 = make_float4(acc[4] * inv49, acc[5] * inv49, acc[6] * inv49, acc[7] * inv49);
        float4* o = (float4*)(out + (size_t)warp * 8);
        o[0] = o0;
        o[1] = o1;
    }
}

// ---------------------------------------------------------------------------
extern "C" void kernel_launch(void* const* d_in, const int* in_sizes, int n_in,
                              void* d_out, int out_size) {
    const float* conv = (const float*)d_in[0];   // [8,1024,1024] fp32
    const int*   rois = (const int*)d_in[1];     // [n,4] int32
    float*       out  = (float*)d_out;           // [n,8] fp32
    const int n = in_sizes[1] / 4;

    rowscan_kernel<<<HH, 256>>>(conv);
    colscan_kernel<<<NSEG * (NCOL / 256), 256>>>();
    pool_kernel   <<<(n + 7) / 8, 256>>>(rois, out, n);
}

// round 6
// speedup vs baseline: 1.6213x; 1.0667x over previous
#include <cuda_runtime.h>
#include <cuda_bf16.h>

// Problem constants (fixed by reference setup_inputs)
#define HH   1024
#define WW   1024
#define NC   8
#define NCOL (WW * NC)      // 8192 flat columns in [y][x][c] layout
#define NSEG 32
#define SEGH (HH / NSEG)    // 32
#define NPOOL 7

// Scratch: SAT in channel-last layout [y][x][c], fp32. 32 MB (fits L2).
__device__ float g_sat[(size_t)HH * NCOL];
// Decoupled-lookback links per (seg, flat col):
//   {float_bits:32 | flags} flags: bit0 = aggregate ready, bit1 = inclusive.
__device__ unsigned long long g_link[NSEG * NCOL];   // 2 MB

// ---------------------------------------------------------------------------
// Pass 1: inclusive row scan (along x), 4 elements/thread, channel-at-a-time
// (low register pressure): raw prefixes go straight to smem, offsets are
// applied at store time via a per-(owner,channel) offset table.
// One block (256 threads) per row y. Also resets lookback links.
// ---------------------------------------------------------------------------
__global__ void __launch_bounds__(256) rowscan_kernel(const float* __restrict__ in) {
    __shared__ float sbuf[256 * 33];   // raw prefix values, padded (33.8 KB)
    __shared__ float soff[256 * 8];    // per-owner per-channel offsets (8 KB)
    __shared__ float wsum[NC][8];

    const int y    = blockIdx.x;
    const int t    = threadIdx.x;
    const int lane = t & 31;
    const int wid  = t >> 5;

    // Reset lookback links: NSEG*NCOL = 262144 entries / 1024 rows = 256 each.
    g_link[(size_t)y * 256 + t] = 0ull;

    float excl[NC];
    #pragma unroll
    for (int c = 0; c < NC; ++c) {
        float4 vv = ((const float4*)(in + (size_t)c * (HH * WW) + (size_t)y * WW))[t];
        vv.y += vv.x; vv.z += vv.y; vv.w += vv.z;
        float s = vv.w;
        #pragma unroll
        for (int d = 1; d < 32; d <<= 1) {
            float nb = __shfl_up_sync(0xffffffffu, s, d);
            if (lane >= d) s += nb;
        }
        excl[c] = s - vv.w;
        if (lane == 31) wsum[c][wid] = s;
        // raw (offset-less) values -> padded smem: idx = 33*t + 8*i + c
        sbuf[33 * t + c]      = vv.x;
        sbuf[33 * t + 8 + c]  = vv.y;
        sbuf[33 * t + 16 + c] = vv.z;
        sbuf[33 * t + 24 + c] = vv.w;
    }
    __syncthreads();

    // Warp 0 scans the 8 warp totals per channel (width-8 groups).
    if (wid == 0) {
        #pragma unroll
        for (int c = 0; c < NC; ++c) {
            float w = (lane < 8) ? wsum[c][lane] : 0.f;
            #pragma unroll
            for (int d = 1; d < 8; d <<= 1) {
                float nb = __shfl_up_sync(0xffffffffu, w, d);
                if ((lane & 7) >= d) w += nb;
            }
            if (lane < 8) wsum[c][lane] = w;
        }
    }
    __syncthreads();

    // Per-thread per-channel offsets (everything left of this thread's 4 x).
    #pragma unroll
    for (int c = 0; c < NC; ++c)
        soff[t * 8 + c] = excl[c] + (wid ? wsum[c][wid - 1] : 0.f);
    __syncthreads();

    // Coalesced float4 stores. Output float o = x*8+c; owner thread tp = o/32;
    // smem idx = o + o/32 = 33*tp + 8*(x%4) + c. Channels per float4: (s&1)*4.
    float4* out4 = (float4*)(g_sat + (size_t)y * NCOL);
    #pragma unroll
    for (int j = 0; j < 8; ++j) {
        const int s_  = j * 256 + t;
        const int o   = s_ * 4;
        const int idx = o + (o >> 5);
        const int tp  = o >> 5;
        const int cLo = (s_ & 1) * 4;
        float4 ofs = *((const float4*)&soff[tp * 8 + cLo]);
        float4 val = make_float4(sbuf[idx]     + ofs.x,
                                 sbuf[idx + 1] + ofs.y,
                                 sbuf[idx + 2] + ofs.z,
                                 sbuf[idx + 3] + ofs.w);
        out4[s_] = val;
    }
}

// ---------------------------------------------------------------------------
// Pass 2: single-pass column cumsum, decoupled lookback with early aggregate
// publish (no serial cross-segment chain). Block = 1 segment (32 rows) x 256
// columns; seg ascends with blockIdx (deps point to lower bids -> no deadlock).
// ---------------------------------------------------------------------------
__global__ void __launch_bounds__(256) colscan_kernel() {
    const int tid   = threadIdx.x;
    const int seg   = blockIdx.x >> 5;       // NCOL/256 = 32 chunks per seg
    const int chunk = blockIdx.x & 31;
    const int f     = chunk * 256 + tid;

    float* base = g_sat + (size_t)seg * SEGH * NCOL + f;

    // Local inclusive prefix over the 32 segment rows (reg-resident).
    float pref[SEGH];
    float s = 0.f;
    #pragma unroll
    for (int k = 0; k < SEGH; ++k) {
        s += __ldcg(base + (size_t)k * NCOL);
        pref[k] = s;
    }

    // Publish local aggregate immediately (flag = 1).
    if (seg < NSEG - 1) {
        unsigned long long agg =
            ((unsigned long long)__float_as_uint(s) << 32) | 1ull;
        atomicExch(&g_link[(size_t)seg * NCOL + f], agg);
    }

    // Lookback: walk predecessors, summing aggregates, stop at an inclusive.
    float off = 0.f;
    for (int i = seg - 1; i >= 0; --i) {
        unsigned long long u;
        do {
            u = atomicAdd(&g_link[(size_t)i * NCOL + f], 0ull);
        } while (!(u & 1ull));
        off += __uint_as_float((unsigned)(u >> 32));
        if (u & 2ull) break;       // that value was inclusive -> done
    }

    // Publish inclusive prefix (flag = 3).
    if (seg < NSEG - 1) {
        unsigned long long inc =
            ((unsigned long long)__float_as_uint(off + s) << 32) | 3ull;
        atomicExch(&g_link[(size_t)seg * NCOL + f], inc);
    }

    // Finalize in place.
    #pragma unroll
    for (int k = 0; k < SEGH; ++k)
        __stcg(base + (size_t)k * NCOL, pref[k] + off);
}

// ---------------------------------------------------------------------------
// Pass 3: adaptive 7x7 ROI pooling + final mean. One warp per ROI.
// g_sat holds inclusive SAT; padded sat(y,x) = g_sat[y-1][x-1] (0 at borders).
// ---------------------------------------------------------------------------
__device__ __forceinline__ void load8(int y, int x, float v[8]) {
    if (y > 0 && x > 0) {
        const float4* p = (const float4*)(g_sat + ((size_t)(y - 1) * WW + (x - 1)) * NC);
        float4 a = p[0], b = p[1];
        v[0] = a.x; v[1] = a.y; v[2] = a.z; v[3] = a.w;
        v[4] = b.x; v[5] = b.y; v[6] = b.z; v[7] = b.w;
    } else {
        #pragma unroll
        for (int c = 0; c < 8; ++c) v[c] = 0.f;
    }
}

__global__ void __launch_bounds__(256) pool_kernel(const int* __restrict__ rois,
                                                   float* __restrict__ out, int n) {
    const int warp = (blockIdx.x * blockDim.x + threadIdx.x) >> 5;
    const int lane = threadIdx.x & 31;
    if (warp >= n) return;

    // rois is int32 [n,4]
    const int4 R = ((const int4*)rois)[warp];
    const int ymin = R.x >> 5;            // // FEAT_STRIDE (=32)
    const int xmin = R.y >> 5;
    const int ymax = (R.z >> 5) + 1;      // exclusive
    const int xmax = (R.w >> 5) + 1;
    const int leny = ymax - ymin;
    const int lenx = xmax - xmin;

    float acc[8];
    #pragma unroll
    for (int c = 0; c < 8; ++c) acc[c] = 0.f;

    for (int bin = lane; bin < 49; bin += 32) {
        const int i = bin / 7;
        const int j = bin - i * 7;
        const int ylo = ymin + (i * leny) / NPOOL;
        const int yhi = ymin + ((i + 1) * leny + NPOOL - 1) / NPOOL;
        const int xlo = xmin + (j * lenx) / NPOOL;
        const int xhi = xmin + ((j + 1) * lenx + NPOOL - 1) / NPOOL;

        float Shh[8], Slh[8], Shl[8], Sll[8];
        load8(yhi, xhi, Shh);
        load8(ylo, xhi, Slh);
        load8(yhi, xlo, Shl);
        load8(ylo, xlo, Sll);

        const int   area = (yhi - ylo) * (xhi - xlo);
        const float w    = 1.f / (float)area;
        #pragma unroll
        for (int c = 0; c < 8; ++c)
            acc[c] += w * ((Shh[c] - Slh[c]) - (Shl[c] - Sll[c]));
    }

    #pragma unroll
    for (int c = 0; c < 8; ++c) {
        #pragma unroll
        for (int d = 16; d; d >>= 1)
            acc[c] += __shfl_xor_sync(0xffffffffu, acc[c], d);
    }

    if (lane == 0) {
        const float inv49 = 1.f / 49.f;
        float4 o0 = make_float4(acc[0] * inv49, acc[1] * inv49, acc[2] * inv49, acc[3] * inv49);
        float4 o1 = make_float4(acc[4] * inv49, acc[5] * inv49, acc[6] * inv49, acc[7] * inv49);
        float4* o = (float4*)(out + (size_t)warp * 8);
        o[0] = o0;
        o[1] = o1;
    }
}

// ---------------------------------------------------------------------------
extern "C" void kernel_launch(void* const* d_in, const int* in_sizes, int n_in,
                              void* d_out, int out_size) {
    const float* conv = (const float*)d_in[0];   // [8,1024,1024] fp32
    const int*   rois = (const int*)d_in[1];     // [n,4] int32
    float*       out  = (float*)d_out;           // [n,8] fp32
    const int n = in_sizes[1] / 4;

    rowscan_kernel<<<HH, 256>>>(conv);
    colscan_kernel<<<NSEG * (NCOL / 256), 256>>>();
    pool_kernel   <<<(n + 7) / 8, 256>>>(rois, out, n);
}

// round 7
// speedup vs baseline: 1.6947x; 1.0453x over previous
#include <cuda_runtime.h>
#include <cuda_bf16.h>

// Problem constants (fixed by reference setup_inputs)
#define HH   1024
#define WW   1024
#define NC   8
#define NCOL (WW * NC)      // 8192 flat columns in [y][x][c] layout
#define NSEG 32
#define SEGH (HH / NSEG)    // 32
#define NPOOL 7

// Scratch: SAT in channel-last layout [y][x][c], fp32. 32 MB (fits L2).
__device__ float g_sat[(size_t)HH * NCOL];
// Decoupled-lookback links per (seg, flat col):
//   {float_bits:32 | flags} flags: bit0 = aggregate ready, bit1 = inclusive.
__device__ unsigned long long g_link[NSEG * NCOL];   // 2 MB

// ---------------------------------------------------------------------------
// Pass 1: inclusive row scan. 128 threads/row, 8 consecutive x per thread
// (seq-8 in-register prefix -> half the SHFL work of seq-4). Channels in two
// halves of 4 to bound register pressure. Transpose staging: full row in
// [x][c] order with 32B-unit XOR swizzle us = x ^ ((x>>3)&3); all smem ops
// are 128-bit vectors. One block per row y. Also resets lookback links.
// ---------------------------------------------------------------------------
__global__ void __launch_bounds__(128) rowscan_kernel(const float* __restrict__ in) {
    __shared__ float sbuf[WW * NC];    // 32 KB, unit-swizzled [x][c]
    __shared__ float wsum[NC][4];

    const int y    = blockIdx.x;
    const int t    = threadIdx.x;
    const int lane = t & 31;
    const int wid  = t >> 5;

    // Reset lookback links: 256 per row, 2 per thread.
    g_link[(size_t)y * 256 + t]       = 0ull;
    g_link[(size_t)y * 256 + 128 + t] = 0ull;

    #pragma unroll
    for (int h = 0; h < 2; ++h) {
        float r[4][8];                 // [q = channel-in-half][i = x-in-thread]
        float excl[4];

        // Load 8 consecutive x (two float4) per channel; seq prefix (7 FADD).
        #pragma unroll
        for (int q = 0; q < 4; ++q) {
            const int c = h * 4 + q;
            const float4* p = (const float4*)(in + (size_t)c * (HH * WW) + (size_t)y * WW);
            float4 A = p[2 * t];
            float4 B = p[2 * t + 1];
            r[q][0] = A.x;           r[q][1] = A.y + r[q][0];
            r[q][2] = A.z + r[q][1]; r[q][3] = A.w + r[q][2];
            r[q][4] = B.x + r[q][3]; r[q][5] = B.y + r[q][4];
            r[q][6] = B.z + r[q][5]; r[q][7] = B.w + r[q][6];
        }

        // Warp inclusive scan of per-thread totals.
        #pragma unroll
        for (int q = 0; q < 4; ++q) {
            float s = r[q][7];
            #pragma unroll
            for (int d = 1; d < 32; d <<= 1) {
                float nb = __shfl_up_sync(0xffffffffu, s, d);
                if (lane >= d) s += nb;
            }
            excl[q] = s - r[q][7];
            if (lane == 31) wsum[h * 4 + q][wid] = s;
        }
        __syncthreads();

        // Combine 4 warp totals per channel (lanes 0..15 of warp 0).
        if (t < 16) {
            const int c = h * 4 + (t >> 2);
            const int w = t & 3;
            float s = wsum[c][w];
            float n1 = __shfl_up_sync(0xffffu, s, 1);
            if (w >= 1) s += n1;
            float n2 = __shfl_up_sync(0xffffu, s, 2);
            if (w >= 2) s += n2;
            wsum[c][w] = s;
        }
        __syncthreads();

        // Apply offsets in registers, then vector-store to swizzled smem:
        // unit u = x holds channels 0..7 of x; float idx = us*8 + c.
        #pragma unroll
        for (int q = 0; q < 4; ++q) {
            const int c = h * 4 + q;
            const float off = excl[q] + (wid ? wsum[c][wid - 1] : 0.f);
            #pragma unroll
            for (int i = 0; i < 8; ++i) r[q][i] += off;
        }
        #pragma unroll
        for (int i = 0; i < 8; ++i) {
            const int x  = 8 * t + i;
            const int us = x ^ (t & 3);            // (x>>3)&3 == t&3 here
            *(float4*)&sbuf[us * 8 + h * 4] =
                make_float4(r[0][i], r[1][i], r[2][i], r[3][i]);
        }
        __syncthreads();
    }

    // Coalesced drain: output float4 F -> x = F>>1, half = F&1,
    // smem chunk = swz(x)*2 + half.
    const float4* s4  = (const float4*)sbuf;
    float4* out4 = (float4*)(g_sat + (size_t)y * NCOL);
    #pragma unroll
    for (int j = 0; j < 16; ++j) {
        const int F  = j * 128 + t;
        const int x  = F >> 1;
        const int us = x ^ ((x >> 3) & 3);
        out4[F] = s4[us * 2 + (F & 1)];
    }
}

// ---------------------------------------------------------------------------
// Pass 2: single-pass column cumsum, decoupled lookback with early aggregate
// publish (no serial cross-segment chain). Block = 1 segment (32 rows) x 256
// columns; seg ascends with blockIdx (deps point to lower bids -> no deadlock).
// ---------------------------------------------------------------------------
__global__ void __launch_bounds__(256) colscan_kernel() {
    const int tid   = threadIdx.x;
    const int seg   = blockIdx.x >> 5;       // NCOL/256 = 32 chunks per seg
    const int chunk = blockIdx.x & 31;
    const int f     = chunk * 256 + tid;

    float* base = g_sat + (size_t)seg * SEGH * NCOL + f;

    // Local inclusive prefix over the 32 segment rows (reg-resident).
    float pref[SEGH];
    float s = 0.f;
    #pragma unroll
    for (int k = 0; k < SEGH; ++k) {
        s += __ldcg(base + (size_t)k * NCOL);
        pref[k] = s;
    }

    // Publish local aggregate immediately (flag = 1).
    if (seg < NSEG - 1) {
        unsigned long long agg =
            ((unsigned long long)__float_as_uint(s) << 32) | 1ull;
        atomicExch(&g_link[(size_t)seg * NCOL + f], agg);
    }

    // Lookback: walk predecessors, summing aggregates, stop at an inclusive.
    float off = 0.f;
    for (int i = seg - 1; i >= 0; --i) {
        unsigned long long u;
        do {
            u = atomicAdd(&g_link[(size_t)i * NCOL + f], 0ull);
        } while (!(u & 1ull));
        off += __uint_as_float((unsigned)(u >> 32));
        if (u & 2ull) break;       // that value was inclusive -> done
    }

    // Publish inclusive prefix (flag = 3).
    if (seg < NSEG - 1) {
        unsigned long long inc =
            ((unsigned long long)__float_as_uint(off + s) << 32) | 3ull;
        atomicExch(&g_link[(size_t)seg * NCOL + f], inc);
    }

    // Finalize in place.
    #pragma unroll
    for (int k = 0; k < SEGH; ++k)
        __stcg(base + (size_t)k * NCOL, pref[k] + off);
}

// ---------------------------------------------------------------------------
// Pass 3: adaptive 7x7 ROI pooling + final mean. One warp per ROI.
// g_sat holds inclusive SAT; padded sat(y,x) = g_sat[y-1][x-1] (0 at borders).
// ---------------------------------------------------------------------------
__device__ __forceinline__ void load8(int y, int x, float v[8]) {
    if (y > 0 && x > 0) {
        const float4* p = (const float4*)(g_sat + ((size_t)(y - 1) * WW + (x - 1)) * NC);
        float4 a = p[0], b = p[1];
        v[0] = a.x; v[1] = a.y; v[2] = a.z; v[3] = a.w;
        v[4] = b.x; v[5] = b.y; v[6] = b.z; v[7] = b.w;
    } else {
        #pragma unroll
        for (int c = 0; c < 8; ++c) v[c] = 0.f;
    }
}

__global__ void __launch_bounds__(256) pool_kernel(const int* __restrict__ rois,
                                                   float* __restrict__ out, int n) {
    const int warp = (blockIdx.x * blockDim.x + threadIdx.x) >> 5;
    const int lane = threadIdx.x & 31;
    if (warp >= n) return;

    // rois is int32 [n,4]
    const int4 R = ((const int4*)rois)[warp];
    const int ymin = R.x >> 5;            // // FEAT_STRIDE (=32)
    const int xmin = R.y >> 5;
    const int ymax = (R.z >> 5) + 1;      // exclusive
    const int xmax = (R.w >> 5) + 1;
    const int leny = ymax - ymin;
    const int lenx = xmax - xmin;

    float acc[8];
    #pragma unroll
    for (int c = 0; c < 8; ++c) acc[c] = 0.f;

    for (int bin = lane; bin < 49; bin += 32) {
        const int i = bin / 7;
        const int j = bin - i * 7;
        const int ylo = ymin + (i * leny) / NPOOL;
        const int yhi = ymin + ((i + 1) * leny + NPOOL - 1) / NPOOL;
        const int xlo = xmin + (j * lenx) / NPOOL;
        const int xhi = xmin + ((j + 1) * lenx + NPOOL - 1) / NPOOL;

        float Shh[8], Slh[8], Shl[8], Sll[8];
        load8(yhi, xhi, Shh);
        load8(ylo, xhi, Slh);
        load8(yhi, xlo, Shl);
        load8(ylo, xlo, Sll);

        const int   area = (yhi - ylo) * (xhi - xlo);
        const float w    = 1.f / (float)area;
        #pragma unroll
        for (int c = 0; c < 8; ++c)
            acc[c] += w * ((Shh[c] - Slh[c]) - (Shl[c] - Sll[c]));
    }

    #pragma unroll
    for (int c = 0; c < 8; ++c) {
        #pragma unroll
        for (int d = 16; d; d >>= 1)
            acc[c] += __shfl_xor_sync(0xffffffffu, acc[c], d);
    }

    if (lane == 0) {
        const float inv49 = 1.f / 49.f;
        float4 o0 = make_float4(acc[0] * inv49, acc[1] * inv49, acc[2] * inv49, acc[3] * inv49);
        float4 o1 = make_float4(acc[4] * inv49, acc[5] * inv49, acc[6] * inv49, acc[7] * inv49);
        float4* o = (float4*)(out + (size_t)warp * 8);
        o[0] = o0;
        o[1] = o1;
    }
}

// ---------------------------------------------------------------------------
extern "C" void kernel_launch(void* const* d_in, const int* in_sizes, int n_in,
                              void* d_out, int out_size) {
    const float* conv = (const float*)d_in[0];   // [8,1024,1024] fp32
    const int*   rois = (const int*)d_in[1];     // [n,4] int32
    float*       out  = (float*)d_out;           // [n,8] fp32
    const int n = in_sizes[1] / 4;

    rowscan_kernel<<<HH, 128>>>(conv);
    colscan_kernel<<<NSEG * (NCOL / 256), 256>>>();
    pool_kernel   <<<(n + 7) / 8, 256>>>(rois, out, n);
}